// round 13
// baseline (speedup 1.0000x reference)
#include <cuda_runtime.h>
#include <math.h>

#define STATE_DIM 64
#define HID 512
#define ACT 8
#define BATCH 128
#define SEQ 16
#define TSTEPS (SEQ*BATCH)   // 2048 sequential LSTM steps
#define G4 (4*HID)
#define N0 64
#define N1 64
#define NCTA (N0+N1)
#define TPB 512
#define SENT 0x7FBFFFFFu     // NaN payload: impossible h bit pattern
#define FULLM 0xffffffffu

// ---------------- scratch ---------------------------------------------------
__device__ float g_x [BATCH*HID];
__device__ float g_A0[BATCH*G4];
__device__ float g_h0[TSTEPS*HID];
__device__ float g_h1[TSTEPS*HID];

// ---------------- helpers ---------------------------------------------------
__device__ __forceinline__ float tanhapx(float x) {
    float y; asm("tanh.approx.f32 %0, %1;" : "=f"(y) : "f"(x)); return y;
}
__device__ __forceinline__ float sigf(float x) { return 0.5f*tanhapx(0.5f*x) + 0.5f; }

__device__ __forceinline__ unsigned ldvol32(const unsigned* p) {
    unsigned v;
    asm volatile("ld.volatile.global.u32 %0, [%1];" : "=r"(v) : "l"(p) : "memory");
    return v;
}
__device__ __forceinline__ uint2 ldvol64(const uint2* p) {
    uint2 v;
    asm volatile("ld.volatile.global.v2.u32 {%0,%1}, [%2];"
                 : "=r"(v.x), "=r"(v.y) : "l"(p) : "memory");
    return v;
}
__device__ __forceinline__ void stvolf(float* p, float v) {
    asm volatile("st.volatile.global.f32 [%0], %1;" :: "l"(p), "f"(v) : "memory");
}
__device__ __forceinline__ unsigned long long fma2(unsigned long long a,
                                                   unsigned long long b,
                                                   unsigned long long c) {
    unsigned long long d;
    asm("fma.rn.f32x2 %0, %1, %2, %3;" : "=l"(d) : "l"(a), "l"(b), "l"(c));
    return d;
}
__device__ __forceinline__ float fsum(unsigned long long v) {
    float x, y;
    asm("mov.b64 {%0,%1}, %2;" : "=f"(x), "=f"(y) : "l"(v));
    return x + y;
}

// Pipelined 4-deep spin: keeps 4 independent volatile loads in flight so the
// warp samples L2 every ~1/4 round trip instead of every full round trip.
__device__ __forceinline__ unsigned spin32(const unsigned* p) {
    unsigned a = ldvol32(p), b = ldvol32(p), c = ldvol32(p), d = ldvol32(p);
    for (;;) {
        if (__all_sync(FULLM, a != SENT)) return a;
        a = ldvol32(p);
        if (__all_sync(FULLM, b != SENT)) return b;
        b = ldvol32(p);
        if (__all_sync(FULLM, c != SENT)) return c;
        c = ldvol32(p);
        if (__all_sync(FULLM, d != SENT)) return d;
        d = ldvol32(p);
    }
}
__device__ __forceinline__ uint2 spin64(const uint2* p) {
    uint2 a = ldvol64(p), b = ldvol64(p), c = ldvol64(p), d = ldvol64(p);
    for (;;) {
        if (__all_sync(FULLM, (a.x != SENT) & (a.y != SENT))) return a;
        a = ldvol64(p);
        if (__all_sync(FULLM, (b.x != SENT) & (b.y != SENT))) return b;
        b = ldvol64(p);
        if (__all_sync(FULLM, (c.x != SENT) & (c.y != SENT))) return c;
        c = ldvol64(p);
        if (__all_sync(FULLM, (d.x != SENT) & (d.y != SENT))) return d;
        d = ldvol64(p);
    }
}

// ---------------- K0: sentinel-fill h histories (graph replays) -------------
__global__ void k_init() {
    unsigned i = blockIdx.x*blockDim.x + threadIdx.x;   // 1024*256 = 262144
    uint4 s = make_uint4(SENT, SENT, SENT, SENT);
    ((uint4*)g_h0)[i] = s;
    ((uint4*)g_h1)[i] = s;
}

// ---------------- K1: LayerNorm + pre-linear --------------------------------
__global__ void k_pre(const float* __restrict__ state, const float* __restrict__ lng,
                      const float* __restrict__ lnb,   const float* __restrict__ Wpre,
                      const float* __restrict__ bpre) {
    __shared__ float xn[STATE_DIM];
    __shared__ float stats[2];
    int b = blockIdx.x, tid = threadIdx.x;
    if (tid < STATE_DIM) xn[tid] = state[b*STATE_DIM + tid];
    __syncthreads();
    if (tid == 0) {
        float mu = 0.f;
        for (int k = 0; k < STATE_DIM; k++) mu += xn[k];
        mu *= (1.f/STATE_DIM);
        float var = 0.f;
        for (int k = 0; k < STATE_DIM; k++) { float d = xn[k]-mu; var += d*d; }
        var *= (1.f/STATE_DIM);
        stats[0] = mu; stats[1] = rsqrtf(var + 1e-5f);
    }
    __syncthreads();
    float mu = stats[0], rs = stats[1];
    if (tid < STATE_DIM) xn[tid] = (xn[tid]-mu)*rs*lng[tid] + lnb[tid];
    __syncthreads();
    float acc = bpre[tid];
    const float* w = Wpre + tid*STATE_DIM;
    #pragma unroll 16
    for (int k = 0; k < STATE_DIM; k++) acc = fmaf(w[k], xn[k], acc);
    g_x[b*HID + tid] = acc;
}

// ---------------- K2: A0 = W_ih0@x + b_ih0 + b_hh0 --------------------------
__global__ void k_a0(const float* __restrict__ Wih, const float* __restrict__ bih,
                     const float* __restrict__ bhh) {
    int tid = threadIdx.x, lane = tid & 31, warp = tid >> 5;
    int row = blockIdx.x*8 + warp;
    float wr[16];
    const float* w = Wih + (size_t)row*HID + lane*16;
    #pragma unroll
    for (int i = 0; i < 16; i++) wr[i] = w[i];
    float bsum = bih[row] + bhh[row];
    __shared__ float xs[HID];
    for (int b = 0; b < BATCH; b++) {
        __syncthreads();
        for (int i = tid; i < HID; i += 256) xs[i] = g_x[b*HID + i];
        __syncthreads();
        float a = 0.f;
        #pragma unroll
        for (int i = 0; i < 16; i++) a = fmaf(wr[i], xs[lane*16 + i], a);
        #pragma unroll
        for (int o = 16; o > 0; o >>= 1) a += __shfl_xor_sync(FULLM, a, o);
        if (lane == 0) g_A0[b*G4 + row] = a + bsum;
    }
}

// ---------------- K_LSTM: R8 skeleton + pipelined poll + fast tail ----------
// Each compute warp polls+stages its own h slice (4-deep pipelined sentinel
// spin), FFMA2 matvec, STS partial, one __syncthreads, warp-0 tail with
// pre-shuffle activation.
__global__ void __launch_bounds__(TPB, 1)
k_lstm(const float* __restrict__ Wih, const float* __restrict__ Whh,
       const float* __restrict__ bih, const float* __restrict__ bhh) {
    __shared__ float hbuf[2*HID];
    __shared__ float red[16*33];
    __shared__ float As[BATCH*32];
    __shared__ float bias1[32];
    const int tid = threadIdx.x, lane = tid & 31, warp = tid >> 5;
    const int j = lane & 7;
    float c_state = 0.f;

    if (blockIdx.x < N0) {
        // ===================== layer-0 group =====================
        const int g = blockIdx.x;
        const int grow = (lane>>3)*HID + g*8 + j;
        unsigned long long w2[16];                 // 32 cols [warp*32,+32)
        {
            const ulonglong2* wp = (const ulonglong2*)(Whh + (size_t)grow*HID + warp*32);
            #pragma unroll
            for (int i = 0; i < 8; i++) { ulonglong2 v = wp[i]; w2[2*i] = v.x; w2[2*i+1] = v.y; }
        }
        for (int i = tid; i < BATCH*32; i += TPB) {
            int bb = i >> 5, lr = i & 31;
            As[i] = g_A0[bb*G4 + (lr>>3)*HID + g*8 + (lr&7)];
        }
        __syncthreads();

        for (int t = 0; t < TSTEPS; t++) {
            if (t > 0) {
                const unsigned* p =
                    (const unsigned*)(g_h0 + (size_t)(t-1)*HID + warp*32) + lane;
                hbuf[warp*32 + lane] = __uint_as_float(spin32(p));
            } else {
                hbuf[warp*32 + lane] = 0.f;
            }
            __syncwarp();
            unsigned long long a0 = 0ull, a1 = 0ull;
            const ulonglong2* hp2 = (const ulonglong2*)(hbuf + warp*32);
            #pragma unroll
            for (int i = 0; i < 8; i++) {
                ulonglong2 v = hp2[i];
                a0 = fma2(w2[2*i],   v.x, a0);
                a1 = fma2(w2[2*i+1], v.y, a1);
            }
            red[warp*33 + lane] = fsum(a0) + fsum(a1);
            __syncthreads();                                      // barB
            if (warp == 0) {
                float s[16];
                #pragma unroll
                for (int ww = 0; ww < 16; ww++) s[ww] = red[ww*33 + lane];
                float q0 = (s[0]+s[1]) + (s[2]+s[3]);
                float q1 = (s[4]+s[5]) + (s[6]+s[7]);
                float q2 = (s[8]+s[9]) + (s[10]+s[11]);
                float q3 = (s[12]+s[13]) + (s[14]+s[15]);
                float gv = As[(t & (BATCH-1))*32 + lane] + ((q0+q1) + (q2+q3));
                float act = (lane >= 16 && lane < 24) ? tanhapx(gv) : sigf(gv);
                float vi = __shfl_sync(FULLM, act, j);
                float vf = __shfl_sync(FULLM, act, 8 + j);
                float vg = __shfl_sync(FULLM, act, 16 + j);
                float vo = __shfl_sync(FULLM, act, 24 + j);
                c_state = vf*c_state + vi*vg;
                float hv = vo*tanhapx(c_state);
                if (lane < 8) stvolf(g_h0 + (size_t)t*HID + g*8 + lane, hv);
            }
        }
    } else {
        // ===================== layer-1 group =====================
        const int g = blockIdx.x - N0;
        const int grow = (lane>>3)*HID + g*8 + j;
        unsigned long long w2[32];                 // 64 cols [warp*64,+64) of [h0|h1]
        {
            const ulonglong2* wp = (warp < 8)
                ? (const ulonglong2*)(Wih + (size_t)G4*HID + (size_t)grow*HID + warp*64)
                : (const ulonglong2*)(Whh + (size_t)G4*HID + (size_t)grow*HID + (warp-8)*64);
            #pragma unroll
            for (int i = 0; i < 16; i++) { ulonglong2 v = wp[i]; w2[2*i] = v.x; w2[2*i+1] = v.y; }
        }
        if (tid < 32)
            bias1[tid] = bih[G4 + (tid>>3)*HID + g*8 + (tid&7)]
                       + bhh[G4 + (tid>>3)*HID + g*8 + (tid&7)];
        __syncthreads();

        for (int t = 0; t < TSTEPS; t++) {
            if (warp < 8) {                        // h0[t]: produced ahead, cheap poll
                const uint2* p =
                    (const uint2*)(g_h0 + (size_t)t*HID + warp*64) + lane;
                uint2 v = spin64(p);
                *(float2*)(hbuf + warp*64 + 2*lane) =
                    make_float2(__uint_as_float(v.x), __uint_as_float(v.y));
            } else if (t > 0) {                    // h1[t-1]: the recurrence
                const uint2* p =
                    (const uint2*)(g_h1 + (size_t)(t-1)*HID + (warp-8)*64) + lane;
                uint2 v = spin64(p);
                *(float2*)(hbuf + warp*64 + 2*lane) =
                    make_float2(__uint_as_float(v.x), __uint_as_float(v.y));
            } else {
                *(float2*)(hbuf + warp*64 + 2*lane) = make_float2(0.f, 0.f);
            }
            __syncwarp();
            unsigned long long a0 = 0ull, a1 = 0ull, a2 = 0ull, a3 = 0ull;
            const ulonglong2* hp2 = (const ulonglong2*)(hbuf + warp*64);
            #pragma unroll
            for (int i = 0; i < 8; i++) {
                ulonglong2 v0 = hp2[2*i], v1 = hp2[2*i+1];
                a0 = fma2(w2[4*i],   v0.x, a0);
                a1 = fma2(w2[4*i+1], v0.y, a1);
                a2 = fma2(w2[4*i+2], v1.x, a2);
                a3 = fma2(w2[4*i+3], v1.y, a3);
            }
            red[warp*33 + lane] = (fsum(a0) + fsum(a1)) + (fsum(a2) + fsum(a3));
            __syncthreads();                                      // barB
            if (warp == 0) {
                float s[16];
                #pragma unroll
                for (int ww = 0; ww < 16; ww++) s[ww] = red[ww*33 + lane];
                float q0 = (s[0]+s[1]) + (s[2]+s[3]);
                float q1 = (s[4]+s[5]) + (s[6]+s[7]);
                float q2 = (s[8]+s[9]) + (s[10]+s[11]);
                float q3 = (s[12]+s[13]) + (s[14]+s[15]);
                float gv = bias1[lane] + ((q0+q1) + (q2+q3));
                float act = (lane >= 16 && lane < 24) ? tanhapx(gv) : sigf(gv);
                float vi = __shfl_sync(FULLM, act, j);
                float vf = __shfl_sync(FULLM, act, 8 + j);
                float vg = __shfl_sync(FULLM, act, 16 + j);
                float vo = __shfl_sync(FULLM, act, 24 + j);
                c_state = vf*c_state + vi*vg;
                float hv = vo*tanhapx(c_state);
                if (lane < 8) stvolf(g_h1 + (size_t)t*HID + g*8 + lane, hv);
            }
        }
    }
}

// ---------------- K3: final FC + tanh ---------------------------------------
__global__ void k_fc(const float* __restrict__ Wfc, const float* __restrict__ bfc,
                     float* __restrict__ out) {
    int s = blockIdx.x;
    int tid = threadIdx.x, lane = tid & 31, a = tid >> 5;
    int tt = s >> 7, b = s & 127;
    const float* h = g_h1 + (size_t)s*HID;
    const float* w = Wfc + a*HID;
    float acc = 0.f;
    for (int k = lane; k < HID; k += 32) acc = fmaf(h[k], w[k], acc);
    #pragma unroll
    for (int o = 16; o > 0; o >>= 1) acc += __shfl_xor_sync(FULLM, acc, o);
    if (lane == 0) out[b*(SEQ*ACT) + tt*ACT + a] = tanhf(acc + bfc[a]);
}

// ---------------------------------------------------------------------------
extern "C" void kernel_launch(void* const* d_in, const int* in_sizes, int n_in,
                              void* d_out, int out_size) {
    const float* state = (const float*)d_in[0];
    const float* lng   = (const float*)d_in[1];
    const float* lnb   = (const float*)d_in[2];
    const float* Wpre  = (const float*)d_in[3];
    const float* bpre  = (const float*)d_in[4];
    const float* Wih   = (const float*)d_in[5];
    const float* Whh   = (const float*)d_in[6];
    const float* bih   = (const float*)d_in[7];
    const float* bhh   = (const float*)d_in[8];
    const float* Wfc   = (const float*)d_in[9];
    const float* bfc   = (const float*)d_in[10];
    float* out = (float*)d_out;

    k_init<<<1024, 256>>>();
    k_pre <<<BATCH, TPB>>>(state, lng, lnb, Wpre, bpre);
    k_a0  <<<G4/8, 256>>>(Wih, bih, bhh);
    k_lstm<<<NCTA, TPB>>>(Wih, Whh, bih, bhh);
    k_fc  <<<TSTEPS, 256>>>(Wfc, bfc, out);
}

// round 14
// speedup vs baseline: 1.5423x; 1.5423x over previous
#include <cuda_runtime.h>
#include <math.h>

#define STATE_DIM 64
#define HID 512
#define ACT 8
#define BATCH 128
#define SEQ 16
#define TSTEPS (SEQ*BATCH)   // 2048 sequential LSTM steps
#define G4 (4*HID)
#define N0 64
#define N1 64
#define NCTA (N0+N1)
#define TPB 512
#define SENT 0x7FBFFFFFu     // NaN payload: impossible h bit pattern
#define FULLM 0xffffffffu

// ---------------- scratch ---------------------------------------------------
__device__ float g_x [BATCH*HID];
__device__ float g_A0[BATCH*G4];
__device__ float g_h0[TSTEPS*HID];
__device__ float g_h1[TSTEPS*HID];

// ---------------- helpers ---------------------------------------------------
__device__ __forceinline__ float tanhapx(float x) {
    float y; asm("tanh.approx.f32 %0, %1;" : "=f"(y) : "f"(x)); return y;
}
__device__ __forceinline__ float sigf(float x) { return 0.5f*tanhapx(0.5f*x) + 0.5f; }

__device__ __forceinline__ unsigned ldvol32(const unsigned* p) {
    unsigned v;
    asm volatile("ld.volatile.global.u32 %0, [%1];" : "=r"(v) : "l"(p) : "memory");
    return v;
}
__device__ __forceinline__ uint2 ldvol64(const uint2* p) {
    uint2 v;
    asm volatile("ld.volatile.global.v2.u32 {%0,%1}, [%2];"
                 : "=r"(v.x), "=r"(v.y) : "l"(p) : "memory");
    return v;
}
__device__ __forceinline__ void stvolf(float* p, float v) {
    asm volatile("st.volatile.global.f32 [%0], %1;" :: "l"(p), "f"(v) : "memory");
}
__device__ __forceinline__ unsigned long long fma2(unsigned long long a,
                                                   unsigned long long b,
                                                   unsigned long long c) {
    unsigned long long d;
    asm("fma.rn.f32x2 %0, %1, %2, %3;" : "=l"(d) : "l"(a), "l"(b), "l"(c));
    return d;
}
__device__ __forceinline__ float fsum(unsigned long long v) {
    float x, y;
    asm("mov.b64 {%0,%1}, %2;" : "=f"(x), "=f"(y) : "l"(v));
    return x + y;
}

// ---------------- K0: sentinel-fill h histories (graph replays) -------------
__global__ void k_init() {
    unsigned i = blockIdx.x*blockDim.x + threadIdx.x;   // 1024*256 = 262144
    uint4 s = make_uint4(SENT, SENT, SENT, SENT);
    ((uint4*)g_h0)[i] = s;
    ((uint4*)g_h1)[i] = s;
}

// ---------------- K1: LayerNorm + pre-linear --------------------------------
__global__ void k_pre(const float* __restrict__ state, const float* __restrict__ lng,
                      const float* __restrict__ lnb,   const float* __restrict__ Wpre,
                      const float* __restrict__ bpre) {
    __shared__ float xn[STATE_DIM];
    __shared__ float stats[2];
    int b = blockIdx.x, tid = threadIdx.x;
    if (tid < STATE_DIM) xn[tid] = state[b*STATE_DIM + tid];
    __syncthreads();
    if (tid == 0) {
        float mu = 0.f;
        for (int k = 0; k < STATE_DIM; k++) mu += xn[k];
        mu *= (1.f/STATE_DIM);
        float var = 0.f;
        for (int k = 0; k < STATE_DIM; k++) { float d = xn[k]-mu; var += d*d; }
        var *= (1.f/STATE_DIM);
        stats[0] = mu; stats[1] = rsqrtf(var + 1e-5f);
    }
    __syncthreads();
    float mu = stats[0], rs = stats[1];
    if (tid < STATE_DIM) xn[tid] = (xn[tid]-mu)*rs*lng[tid] + lnb[tid];
    __syncthreads();
    float acc = bpre[tid];
    const float* w = Wpre + tid*STATE_DIM;
    #pragma unroll 16
    for (int k = 0; k < STATE_DIM; k++) acc = fmaf(w[k], xn[k], acc);
    g_x[b*HID + tid] = acc;
}

// ---------------- K2: A0 = W_ih0@x + b_ih0 + b_hh0 --------------------------
__global__ void k_a0(const float* __restrict__ Wih, const float* __restrict__ bih,
                     const float* __restrict__ bhh) {
    int tid = threadIdx.x, lane = tid & 31, warp = tid >> 5;
    int row = blockIdx.x*8 + warp;
    float wr[16];
    const float* w = Wih + (size_t)row*HID + lane*16;
    #pragma unroll
    for (int i = 0; i < 16; i++) wr[i] = w[i];
    float bsum = bih[row] + bhh[row];
    __shared__ float xs[HID];
    for (int b = 0; b < BATCH; b++) {
        __syncthreads();
        for (int i = tid; i < HID; i += 256) xs[i] = g_x[b*HID + i];
        __syncthreads();
        float a = 0.f;
        #pragma unroll
        for (int i = 0; i < 16; i++) a = fmaf(wr[i], xs[lane*16 + i], a);
        #pragma unroll
        for (int o = 16; o > 0; o >>= 1) a += __shfl_xor_sync(FULLM, a, o);
        if (lane == 0) g_A0[b*G4 + row] = a + bsum;
    }
}

// ---------------- K_LSTM: R8 skeleton + pre-shuffle activation tail ---------
// Each compute warp polls+stages its own h slice (single-load sentinel spin),
// FFMA2 matvec, STS partial, one __syncthreads, warp-0 tail. Tail applies
// each lane's gate nonlinearity BEFORE the shuffles (parallel MUFU), so the
// post-shuffle serial chain is 2 FMA + 1 MUFU + mul.
__global__ void __launch_bounds__(TPB, 1)
k_lstm(const float* __restrict__ Wih, const float* __restrict__ Whh,
       const float* __restrict__ bih, const float* __restrict__ bhh) {
    __shared__ float hbuf[2*HID];
    __shared__ float red[16*33];
    __shared__ float As[BATCH*32];
    __shared__ float bias1[32];
    const int tid = threadIdx.x, lane = tid & 31, warp = tid >> 5;
    const int j = lane & 7;
    float c_state = 0.f;

    if (blockIdx.x < N0) {
        // ===================== layer-0 group =====================
        const int g = blockIdx.x;
        const int grow = (lane>>3)*HID + g*8 + j;
        unsigned long long w2[16];                 // 32 cols [warp*32,+32)
        {
            const ulonglong2* wp = (const ulonglong2*)(Whh + (size_t)grow*HID + warp*32);
            #pragma unroll
            for (int i = 0; i < 8; i++) { ulonglong2 v = wp[i]; w2[2*i] = v.x; w2[2*i+1] = v.y; }
        }
        for (int i = tid; i < BATCH*32; i += TPB) {
            int bb = i >> 5, lr = i & 31;
            As[i] = g_A0[bb*G4 + (lr>>3)*HID + g*8 + (lr&7)];
        }
        __syncthreads();

        for (int t = 0; t < TSTEPS; t++) {
            if (t > 0) {
                const unsigned* p =
                    (const unsigned*)(g_h0 + (size_t)(t-1)*HID + warp*32) + lane;
                unsigned v = ldvol32(p);
                while (!__all_sync(FULLM, v != SENT)) v = ldvol32(p);
                hbuf[warp*32 + lane] = __uint_as_float(v);
            } else {
                hbuf[warp*32 + lane] = 0.f;
            }
            __syncwarp();
            unsigned long long a0 = 0ull, a1 = 0ull;
            const ulonglong2* hp2 = (const ulonglong2*)(hbuf + warp*32);
            #pragma unroll
            for (int i = 0; i < 8; i++) {
                ulonglong2 v = hp2[i];
                a0 = fma2(w2[2*i],   v.x, a0);
                a1 = fma2(w2[2*i+1], v.y, a1);
            }
            red[warp*33 + lane] = fsum(a0) + fsum(a1);
            __syncthreads();                                      // barB
            if (warp == 0) {
                float s[16];
                #pragma unroll
                for (int ww = 0; ww < 16; ww++) s[ww] = red[ww*33 + lane];
                float q0 = (s[0]+s[1]) + (s[2]+s[3]);
                float q1 = (s[4]+s[5]) + (s[6]+s[7]);
                float q2 = (s[8]+s[9]) + (s[10]+s[11]);
                float q3 = (s[12]+s[13]) + (s[14]+s[15]);
                float gv = As[(t & (BATCH-1))*32 + lane] + ((q0+q1) + (q2+q3));
                float act = (lane >= 16 && lane < 24) ? tanhapx(gv) : sigf(gv);
                float vi = __shfl_sync(FULLM, act, j);
                float vf = __shfl_sync(FULLM, act, 8 + j);
                float vg = __shfl_sync(FULLM, act, 16 + j);
                float vo = __shfl_sync(FULLM, act, 24 + j);
                if (lane < 8) {
                    c_state = vf*c_state + vi*vg;
                    stvolf(g_h0 + (size_t)t*HID + g*8 + lane, vo*tanhapx(c_state));
                }
            }
        }
    } else {
        // ===================== layer-1 group =====================
        const int g = blockIdx.x - N0;
        const int grow = (lane>>3)*HID + g*8 + j;
        unsigned long long w2[32];                 // 64 cols [warp*64,+64) of [h0|h1]
        {
            const ulonglong2* wp = (warp < 8)
                ? (const ulonglong2*)(Wih + (size_t)G4*HID + (size_t)grow*HID + warp*64)
                : (const ulonglong2*)(Whh + (size_t)G4*HID + (size_t)grow*HID + (warp-8)*64);
            #pragma unroll
            for (int i = 0; i < 16; i++) { ulonglong2 v = wp[i]; w2[2*i] = v.x; w2[2*i+1] = v.y; }
        }
        if (tid < 32)
            bias1[tid] = bih[G4 + (tid>>3)*HID + g*8 + (tid&7)]
                       + bhh[G4 + (tid>>3)*HID + g*8 + (tid&7)];
        __syncthreads();

        for (int t = 0; t < TSTEPS; t++) {
            if (warp < 8) {                        // h0[t]: produced ahead, cheap poll
                const uint2* p =
                    (const uint2*)(g_h0 + (size_t)t*HID + warp*64) + lane;
                uint2 v = ldvol64(p);
                while (!__all_sync(FULLM, (v.x != SENT) & (v.y != SENT)))
                    v = ldvol64(p);
                *(float2*)(hbuf + warp*64 + 2*lane) =
                    make_float2(__uint_as_float(v.x), __uint_as_float(v.y));
            } else if (t > 0) {                    // h1[t-1]: the recurrence
                const uint2* p =
                    (const uint2*)(g_h1 + (size_t)(t-1)*HID + (warp-8)*64) + lane;
                uint2 v = ldvol64(p);
                while (!__all_sync(FULLM, (v.x != SENT) & (v.y != SENT)))
                    v = ldvol64(p);
                *(float2*)(hbuf + warp*64 + 2*lane) =
                    make_float2(__uint_as_float(v.x), __uint_as_float(v.y));
            } else {
                *(float2*)(hbuf + warp*64 + 2*lane) = make_float2(0.f, 0.f);
            }
            __syncwarp();
            unsigned long long a0 = 0ull, a1 = 0ull, a2 = 0ull, a3 = 0ull;
            const ulonglong2* hp2 = (const ulonglong2*)(hbuf + warp*64);
            #pragma unroll
            for (int i = 0; i < 8; i++) {
                ulonglong2 v0 = hp2[2*i], v1 = hp2[2*i+1];
                a0 = fma2(w2[4*i],   v0.x, a0);
                a1 = fma2(w2[4*i+1], v0.y, a1);
                a2 = fma2(w2[4*i+2], v1.x, a2);
                a3 = fma2(w2[4*i+3], v1.y, a3);
            }
            red[warp*33 + lane] = (fsum(a0) + fsum(a1)) + (fsum(a2) + fsum(a3));
            __syncthreads();                                      // barB
            if (warp == 0) {
                float s[16];
                #pragma unroll
                for (int ww = 0; ww < 16; ww++) s[ww] = red[ww*33 + lane];
                float q0 = (s[0]+s[1]) + (s[2]+s[3]);
                float q1 = (s[4]+s[5]) + (s[6]+s[7]);
                float q2 = (s[8]+s[9]) + (s[10]+s[11]);
                float q3 = (s[12]+s[13]) + (s[14]+s[15]);
                float gv = bias1[lane] + ((q0+q1) + (q2+q3));
                float act = (lane >= 16 && lane < 24) ? tanhapx(gv) : sigf(gv);
                float vi = __shfl_sync(FULLM, act, j);
                float vf = __shfl_sync(FULLM, act, 8 + j);
                float vg = __shfl_sync(FULLM, act, 16 + j);
                float vo = __shfl_sync(FULLM, act, 24 + j);
                if (lane < 8) {
                    c_state = vf*c_state + vi*vg;
                    stvolf(g_h1 + (size_t)t*HID + g*8 + lane, vo*tanhapx(c_state));
                }
            }
        }
    }
}

// ---------------- K3: final FC + tanh ---------------------------------------
__global__ void k_fc(const float* __restrict__ Wfc, const float* __restrict__ bfc,
                     float* __restrict__ out) {
    int s = blockIdx.x;
    int tid = threadIdx.x, lane = tid & 31, a = tid >> 5;
    int tt = s >> 7, b = s & 127;
    const float* h = g_h1 + (size_t)s*HID;
    const float* w = Wfc + a*HID;
    float acc = 0.f;
    for (int k = lane; k < HID; k += 32) acc = fmaf(h[k], w[k], acc);
    #pragma unroll
    for (int o = 16; o > 0; o >>= 1) acc += __shfl_xor_sync(FULLM, acc, o);
    if (lane == 0) out[b*(SEQ*ACT) + tt*ACT + a] = tanhf(acc + bfc[a]);
}

// ---------------------------------------------------------------------------
extern "C" void kernel_launch(void* const* d_in, const int* in_sizes, int n_in,
                              void* d_out, int out_size) {
    const float* state = (const float*)d_in[0];
    const float* lng   = (const float*)d_in[1];
    const float* lnb   = (const float*)d_in[2];
    const float* Wpre  = (const float*)d_in[3];
    const float* bpre  = (const float*)d_in[4];
    const float* Wih   = (const float*)d_in[5];
    const float* Whh   = (const float*)d_in[6];
    const float* bih   = (const float*)d_in[7];
    const float* bhh   = (const float*)d_in[8];
    const float* Wfc   = (const float*)d_in[9];
    const float* bfc   = (const float*)d_in[10];
    float* out = (float*)d_out;

    k_init<<<1024, 256>>>();
    k_pre <<<BATCH, TPB>>>(state, lng, lnb, Wpre, bpre);
    k_a0  <<<G4/8, 256>>>(Wih, bih, bhh);
    k_lstm<<<NCTA, TPB>>>(Wih, Whh, bih, bhh);
    k_fc  <<<TSTEPS, 256>>>(Wfc, bfc, out);
}